// round 1
// baseline (speedup 1.0000x reference)
#include <cuda_runtime.h>
#include <math.h>

// ---------------------------------------------------------------------------
// Problem constants
// ---------------------------------------------------------------------------
constexpr int BATCH = 4;
constexpr int SEQ   = 2048;
constexpr int DIM   = 768;
constexpr int GDIM  = 256;   // per-group embed
constexpr int HDIM  = 64;    // head dim (4 heads per group)
constexpr int MROWS = BATCH * SEQ;   // 8192
constexpr float DT_F  = 0.05f;
constexpr float HJ_HF = 0.05f;

// ---------------------------------------------------------------------------
// Device scratch (no cudaMalloc allowed)
// ---------------------------------------------------------------------------
__device__ float g_h[MROWS * DIM];          // input projection
__device__ float g_qkv[3][MROWS * DIM];     // per-group qkv (B,T,768)
__device__ float g_attn[MROWS * DIM];       // attention outputs, groups at col g*256
__device__ float g_u[MROWS * DIM];          // post out-proj / PDE state, groups at col g*256

// ---------------------------------------------------------------------------
// Generic tiled GEMM with bias: C[M,N] = A[M,K] @ B[K,N] + bias[N]
// BM=128, BN=64, BK=16, 256 threads, 8x4 register tile per thread.
// All M,N,K used here divide the tile sizes exactly.
// ---------------------------------------------------------------------------
__global__ void gemm_bias_kernel(const float* __restrict__ A, int lda,
                                 const float* __restrict__ Bm, int ldb,
                                 const float* __restrict__ bias,
                                 float* __restrict__ C, int ldc,
                                 int K)
{
    __shared__ float As[16][128];   // transposed A tile: As[k][m]
    __shared__ float Bs[16][64];

    const int tid = threadIdx.x;
    const int tx = tid & 15;        // col group (4 cols)
    const int ty = tid >> 4;        // row group (8 rows)
    const int bm = blockIdx.y * 128;
    const int bn = blockIdx.x * 64;

    float acc[8][4];
    #pragma unroll
    for (int i = 0; i < 8; ++i)
        #pragma unroll
        for (int j = 0; j < 4; ++j) acc[i][j] = 0.f;

    const int a_row = tid >> 2;          // 0..63
    const int a_col = (tid & 3) * 4;     // 0,4,8,12
    const int b_row = tid >> 4;          // 0..15
    const int b_col = (tid & 15) * 4;    // 0..60

    for (int k0 = 0; k0 < K; k0 += 16) {
        #pragma unroll
        for (int r = 0; r < 2; ++r) {
            int row = a_row + r * 64;
            float4 v = *reinterpret_cast<const float4*>(
                A + (size_t)(bm + row) * lda + k0 + a_col);
            As[a_col + 0][row] = v.x;
            As[a_col + 1][row] = v.y;
            As[a_col + 2][row] = v.z;
            As[a_col + 3][row] = v.w;
        }
        {
            float4 w = *reinterpret_cast<const float4*>(
                Bm + (size_t)(k0 + b_row) * ldb + bn + b_col);
            *reinterpret_cast<float4*>(&Bs[b_row][b_col]) = w;
        }
        __syncthreads();

        #pragma unroll
        for (int kk = 0; kk < 16; ++kk) {
            float4 a0 = *reinterpret_cast<const float4*>(&As[kk][ty * 8]);
            float4 a1 = *reinterpret_cast<const float4*>(&As[kk][ty * 8 + 4]);
            float4 b0 = *reinterpret_cast<const float4*>(&Bs[kk][tx * 4]);
            const float av[8] = {a0.x, a0.y, a0.z, a0.w, a1.x, a1.y, a1.z, a1.w};
            const float bv[4] = {b0.x, b0.y, b0.z, b0.w};
            #pragma unroll
            for (int i = 0; i < 8; ++i)
                #pragma unroll
                for (int j = 0; j < 4; ++j)
                    acc[i][j] += av[i] * bv[j];
        }
        __syncthreads();
    }

    #pragma unroll
    for (int i = 0; i < 8; ++i) {
        int row = bm + ty * 8 + i;
        int col = bn + tx * 4;
        float4 o;
        o.x = acc[i][0] + bias[col + 0];
        o.y = acc[i][1] + bias[col + 1];
        o.z = acc[i][2] + bias[col + 2];
        o.w = acc[i][3] + bias[col + 3];
        *reinterpret_cast<float4*>(C + (size_t)row * ldc + col) = o;
    }
}

// ---------------------------------------------------------------------------
// Streaming causal attention (flash-style), 64x64 tiles, head_dim = 64.
// grid = (SEQ/64, BATCH*4 heads, 3 groups); block = 256 threads (16x16).
// qkv layout per group: (B,T,768) with q|k|v at col offsets 0/256/512, head h
// at +h*64. Output written into g_attn at column offset g*256 + h*64.
// ---------------------------------------------------------------------------
constexpr int ATT_SMEM_BYTES = (3 * 64 * 68 + 64 * 65) * 4;   // 68,864 B

__global__ void attn_kernel(const float* __restrict__ qkv_all,
                            float* __restrict__ attn_out)
{
    extern __shared__ float sm[];
    float (*Qst)[68] = (float(*)[68])(sm);                 // [d][row]
    float (*Kst)[68] = (float(*)[68])(sm + 64 * 68);       // [d][key]
    float (*Vs )[68] = (float(*)[68])(sm + 2 * 64 * 68);   // [key][d]
    float (*Ps )[65] = (float(*)[65])(sm + 3 * 64 * 68);   // [row][key]

    const int tid = threadIdx.x;
    const int tx = tid & 15;
    const int ty = tid >> 4;
    const int qt = blockIdx.x;
    const int b  = blockIdx.y >> 2;
    const int h  = blockIdx.y & 3;
    const int g  = blockIdx.z;
    const int q0 = qt * 64;

    const float* base = qkv_all + (size_t)g * MROWS * DIM + (size_t)b * SEQ * DIM;
    float* outp = attn_out + (size_t)g * GDIM;
    const int qoff = h * HDIM;
    const int koff = GDIM + h * HDIM;
    const int voff = 2 * GDIM + h * HDIM;

    // Load Q tile, transposed into Qst[d][row]
    {
        const int r  = tid >> 2;
        const int c4 = (tid & 3) * 4;
        #pragma unroll
        for (int it = 0; it < 4; ++it) {
            int c = c4 + it * 16;
            float4 v = *reinterpret_cast<const float4*>(
                base + (size_t)(q0 + r) * DIM + qoff + c);
            Qst[c + 0][r] = v.x; Qst[c + 1][r] = v.y;
            Qst[c + 2][r] = v.z; Qst[c + 3][r] = v.w;
        }
    }

    float mrow[4], lrow[4], oacc[4][4];
    #pragma unroll
    for (int i = 0; i < 4; ++i) {
        mrow[i] = -1e30f; lrow[i] = 0.f;
        #pragma unroll
        for (int j = 0; j < 4; ++j) oacc[i][j] = 0.f;
    }

    for (int jt = 0; jt <= qt; ++jt) {
        __syncthreads();   // prior iteration done reading Kst/Vs/Ps; Q visible
        const int j0 = jt * 64;
        {
            const int r  = tid >> 2;
            const int c4 = (tid & 3) * 4;
            #pragma unroll
            for (int it = 0; it < 4; ++it) {
                int c = c4 + it * 16;
                float4 kv = *reinterpret_cast<const float4*>(
                    base + (size_t)(j0 + r) * DIM + koff + c);
                Kst[c + 0][r] = kv.x; Kst[c + 1][r] = kv.y;
                Kst[c + 2][r] = kv.z; Kst[c + 3][r] = kv.w;
                float4 vv = *reinterpret_cast<const float4*>(
                    base + (size_t)(j0 + r) * DIM + voff + c);
                *reinterpret_cast<float4*>(&Vs[r][c]) = vv;
            }
        }
        __syncthreads();

        // S = Q K^T
        float s[4][4];
        #pragma unroll
        for (int i = 0; i < 4; ++i)
            #pragma unroll
            for (int j = 0; j < 4; ++j) s[i][j] = 0.f;

        #pragma unroll 8
        for (int kk = 0; kk < 64; ++kk) {
            float4 qv = *reinterpret_cast<const float4*>(&Qst[kk][ty * 4]);
            float4 kv = *reinterpret_cast<const float4*>(&Kst[kk][tx * 4]);
            const float qa[4] = {qv.x, qv.y, qv.z, qv.w};
            const float kb[4] = {kv.x, kv.y, kv.z, kv.w};
            #pragma unroll
            for (int i = 0; i < 4; ++i)
                #pragma unroll
                for (int j = 0; j < 4; ++j)
                    s[i][j] += qa[i] * kb[j];
        }

        // scale + causal mask (diagonal tile only)
        #pragma unroll
        for (int i = 0; i < 4; ++i)
            #pragma unroll
            for (int j = 0; j < 4; ++j) {
                s[i][j] *= 0.125f;
                if (jt == qt && (tx * 4 + j) > (ty * 4 + i)) s[i][j] = -1e30f;
            }

        // online softmax, rows owned by 16-lane segments (same ty)
        #pragma unroll
        for (int i = 0; i < 4; ++i) {
            float rm = s[i][0];
            #pragma unroll
            for (int j = 1; j < 4; ++j) rm = fmaxf(rm, s[i][j]);
            rm = fmaxf(rm, __shfl_xor_sync(0xffffffffu, rm, 8, 16));
            rm = fmaxf(rm, __shfl_xor_sync(0xffffffffu, rm, 4, 16));
            rm = fmaxf(rm, __shfl_xor_sync(0xffffffffu, rm, 2, 16));
            rm = fmaxf(rm, __shfl_xor_sync(0xffffffffu, rm, 1, 16));
            float mnew  = fmaxf(mrow[i], rm);
            float alpha = __expf(mrow[i] - mnew);
            mrow[i] = mnew;
            float rs = 0.f;
            #pragma unroll
            for (int j = 0; j < 4; ++j) {
                s[i][j] = __expf(s[i][j] - mnew);
                rs += s[i][j];
            }
            rs += __shfl_xor_sync(0xffffffffu, rs, 8, 16);
            rs += __shfl_xor_sync(0xffffffffu, rs, 4, 16);
            rs += __shfl_xor_sync(0xffffffffu, rs, 2, 16);
            rs += __shfl_xor_sync(0xffffffffu, rs, 1, 16);
            lrow[i] = lrow[i] * alpha + rs;
            #pragma unroll
            for (int j = 0; j < 4; ++j) oacc[i][j] *= alpha;
        }

        // stage P for the PV GEMM
        #pragma unroll
        for (int i = 0; i < 4; ++i)
            #pragma unroll
            for (int j = 0; j < 4; ++j)
                Ps[ty * 4 + i][tx * 4 + j] = s[i][j];
        __syncthreads();

        // O += P V
        #pragma unroll 8
        for (int kk = 0; kk < 64; ++kk) {
            float4 vv = *reinterpret_cast<const float4*>(&Vs[kk][tx * 4]);
            float pv[4];
            #pragma unroll
            for (int i = 0; i < 4; ++i) pv[i] = Ps[ty * 4 + i][kk];
            #pragma unroll
            for (int i = 0; i < 4; ++i) {
                oacc[i][0] += pv[i] * vv.x;
                oacc[i][1] += pv[i] * vv.y;
                oacc[i][2] += pv[i] * vv.z;
                oacc[i][3] += pv[i] * vv.w;
            }
        }
    }

    #pragma unroll
    for (int i = 0; i < 4; ++i) {
        float inv = 1.0f / lrow[i];
        float4 ov = make_float4(oacc[i][0] * inv, oacc[i][1] * inv,
                                oacc[i][2] * inv, oacc[i][3] * inv);
        size_t row = (size_t)b * SEQ + q0 + ty * 4 + i;
        *reinterpret_cast<float4*>(outp + row * DIM + h * HDIM + tx * 4) = ov;
    }
}

// ---------------------------------------------------------------------------
// PDE kernels: one block per (batch, channel) column, column in shared memory.
// u points at the group's column base (stride DIM between timesteps).
// ---------------------------------------------------------------------------
__global__ void pde_sg_kernel(float* __restrict__ u)
{
    const int b = blockIdx.x >> 8;
    const int c = blockIdx.x & 255;
    float* col = u + (size_t)b * SEQ * DIM + c;
    __shared__ float su[SEQ], sw[SEQ];
    const int tid = threadIdx.x;

    for (int t = tid; t < SEQ; t += 256) { su[t] = col[(size_t)t * DIM]; sw[t] = 0.f; }
    __syncthreads();

    for (int step = 0; step < 3; ++step) {
        float dw[8];
        #pragma unroll
        for (int i = 0; i < 8; ++i) {
            int t = tid + i * 256;
            float um = (t > 0)       ? su[t - 1] : 0.f;
            float up = (t < SEQ - 1) ? su[t + 1] : 0.f;
            dw[i] = DT_F * ((um - 2.f * su[t] + up) - sinf(su[t]));
        }
        __syncthreads();
        #pragma unroll
        for (int i = 0; i < 8; ++i) {
            int t = tid + i * 256;
            sw[t] += dw[i];
            su[t] += DT_F * sw[t];
        }
        __syncthreads();
    }
    for (int t = tid; t < SEQ; t += 256) col[(size_t)t * DIM] = su[t];
}

__global__ void pde_kdv_kernel(float* __restrict__ u)
{
    const int b = blockIdx.x >> 8;
    const int c = blockIdx.x & 255;
    float* col = u + (size_t)b * SEQ * DIM + c;
    __shared__ float su[SEQ];
    const int tid = threadIdx.x;

    for (int t = tid; t < SEQ; t += 256) su[t] = col[(size_t)t * DIM];
    __syncthreads();

    for (int step = 0; step < 3; ++step) {
        float du[8];
        #pragma unroll
        for (int i = 0; i < 8; ++i) {
            int t = tid + i * 256;
            float um2 = (t > 1)       ? su[t - 2] : 0.f;
            float um1 = (t > 0)       ? su[t - 1] : 0.f;
            float up1 = (t < SEQ - 1) ? su[t + 1] : 0.f;
            float up2 = (t < SEQ - 2) ? su[t + 2] : 0.f;
            float d1 = 0.5f * (up1 - um1);
            float d3 = 0.5f * (up2 - 2.f * up1 + 2.f * um1 - um2);
            du[i] = DT_F * (-6.f * su[t] * d1 - d3);
        }
        __syncthreads();
        #pragma unroll
        for (int i = 0; i < 8; ++i) {
            int t = tid + i * 256;
            su[t] += du[i];
        }
        __syncthreads();
    }
    for (int t = tid; t < SEQ; t += 256) col[(size_t)t * DIM] = su[t];
}

__global__ void pde_hj_kernel(float* __restrict__ u)
{
    const int b = blockIdx.x >> 8;
    const int c = blockIdx.x & 255;
    float* col = u + (size_t)b * SEQ * DIM + c;
    __shared__ float su[SEQ], sw[SEQ], sf[SEQ];
    const int tid = threadIdx.x;

    for (int t = tid; t < SEQ; t += 256) { su[t] = col[(size_t)t * DIM]; sw[t] = 0.f; }
    __syncthreads();

    for (int step = 0; step < 3; ++step) {
        #pragma unroll
        for (int i = 0; i < 8; ++i) {
            int t = tid + i * 256;
            float v = su[t];
            sf[t] = v - v * v + v * v * v;
        }
        __syncthreads();
        float dw[8];
        #pragma unroll
        for (int i = 0; i < 8; ++i) {
            int t = tid + i * 256;
            float fm  = (t > 0)       ? sf[t - 1] : 0.f;
            float fp  = (t < SEQ - 1) ? sf[t + 1] : 0.f;
            float d2f = fm - 2.f * sf[t] + fp;
            float um2 = (t > 1)       ? su[t - 2] : 0.f;
            float um1 = (t > 0)       ? su[t - 1] : 0.f;
            float up1 = (t < SEQ - 1) ? su[t + 1] : 0.f;
            float up2 = (t < SEQ - 2) ? su[t + 2] : 0.f;
            float d4  = um2 - 4.f * um1 + 6.f * su[t] - 4.f * up1 + up2;
            dw[i] = DT_F * (d2f - HJ_HF * d4);
        }
        __syncthreads();
        #pragma unroll
        for (int i = 0; i < 8; ++i) {
            int t = tid + i * 256;
            sw[t] += dw[i];
            su[t] += DT_F * sw[t];
        }
        __syncthreads();
    }
    for (int t = tid; t < SEQ; t += 256) col[(size_t)t * DIM] = su[t];
}

// ---------------------------------------------------------------------------
// Launch
// ---------------------------------------------------------------------------
extern "C" void kernel_launch(void* const* d_in, const int* in_sizes, int n_in,
                              void* d_out, int out_size)
{
    const float* x      = (const float*)d_in[0];
    const float* in_w   = (const float*)d_in[1];
    const float* in_b   = (const float*)d_in[2];
    const float* qkv_w[3] = {(const float*)d_in[3],  (const float*)d_in[7],  (const float*)d_in[11]};
    const float* qkv_b[3] = {(const float*)d_in[4],  (const float*)d_in[8],  (const float*)d_in[12]};
    const float* ow[3]    = {(const float*)d_in[5],  (const float*)d_in[9],  (const float*)d_in[13]};
    const float* ob[3]    = {(const float*)d_in[6],  (const float*)d_in[10], (const float*)d_in[14]};
    const float* out_w  = (const float*)d_in[15];
    const float* out_b  = (const float*)d_in[16];
    float* out = (float*)d_out;

    float *h, *qkv, *attn, *u;
    cudaGetSymbolAddress((void**)&h,    g_h);
    cudaGetSymbolAddress((void**)&qkv,  g_qkv);
    cudaGetSymbolAddress((void**)&attn, g_attn);
    cudaGetSymbolAddress((void**)&u,    g_u);

    cudaFuncSetAttribute(attn_kernel,
                         cudaFuncAttributeMaxDynamicSharedMemorySize,
                         ATT_SMEM_BYTES);

    // 1) h = x @ in_w + in_b
    gemm_bias_kernel<<<dim3(DIM / 64, MROWS / 128), 256>>>(
        x, DIM, in_w, DIM, in_b, h, DIM, DIM);

    // 2) per-group qkv = h[:, g*256:(g+1)*256] @ qkv_w_g + qkv_b_g
    for (int g = 0; g < 3; ++g) {
        gemm_bias_kernel<<<dim3(768 / 64, MROWS / 128), 256>>>(
            h + g * GDIM, DIM, qkv_w[g], 768, qkv_b[g],
            qkv + (size_t)g * MROWS * DIM, 768, GDIM);
    }

    // 3) causal attention, all 3 groups in one launch
    attn_kernel<<<dim3(SEQ / 64, BATCH * 4, 3), 256, ATT_SMEM_BYTES>>>(qkv, attn);

    // 4) per-group out projection into u (concat layout)
    for (int g = 0; g < 3; ++g) {
        gemm_bias_kernel<<<dim3(GDIM / 64, MROWS / 128), 256>>>(
            attn + g * GDIM, DIM, ow[g], GDIM, ob[g],
            u + g * GDIM, DIM, GDIM);
    }

    // 5) PDE evolutions (in place on u)
    pde_sg_kernel <<<BATCH * GDIM, 256>>>(u + 0 * GDIM);
    pde_kdv_kernel<<<BATCH * GDIM, 256>>>(u + 1 * GDIM);
    pde_hj_kernel <<<BATCH * GDIM, 256>>>(u + 2 * GDIM);

    // 6) out = u @ out_w + out_b
    gemm_bias_kernel<<<dim3(DIM / 64, MROWS / 128), 256>>>(
        u, DIM, out_w, DIM, out_b, out, DIM, DIM);
}